// round 13
// baseline (speedup 1.0000x reference)
#include <cuda_runtime.h>
#include <float.h>
#include <stdint.h>

#define IN_DIM 256
#define OUT_DIM 512
#define MEM_LEN 131072
#define TOPK 16

#define ENC_PARTS 64
#define ROWS_PER_PART (IN_DIM / ENC_PARTS)   // 4

#define DIST_BLOCKS 456                       // 152 SMs * 3 blocks, one wave
#define DIST_NT 512                           // 16 warps
#define WARPS_PER_BLOCK (DIST_NT / 32)
#define NWARPS (DIST_BLOCKS * WARPS_PER_BLOCK)  // 7296
#define ROWS_BASE (MEM_LEN / NWARPS)          // 17
#define ROWS_REM  (MEM_LEN % NWARPS)          // 7040 warps do 18

#define BUF_SMEM (WARPS_PER_BLOCK * 2 * OUT_DIM * 4)   // 64 KB dynamic

#define CAND_LISTS DIST_BLOCKS                // 456 sorted 16-lists
#define CAND_N (CAND_LISTS * TOPK)

__device__ float g_enc[OUT_DIM];
__device__ float g_part[ENC_PARTS * OUT_DIM];
__device__ float g_cand[CAND_N];
__device__ unsigned int g_ctr_enc;
__device__ unsigned int g_ctr_dist;

// ---------------------------------------------------------------------------
// cp.async helpers
// ---------------------------------------------------------------------------
__device__ __forceinline__ void cp_async16(uint32_t saddr, const void* gptr) {
    asm volatile("cp.async.cg.shared.global [%0], [%1], 16;"
                 :: "r"(saddr), "l"(gptr));
}
#define CP_COMMIT() asm volatile("cp.async.commit_group;" ::: "memory")
#define CP_WAIT1()  asm volatile("cp.async.wait_group 1;"  ::: "memory")

// stage one 2KB row: lane copies 16B in each 512B quarter (coalesced)
__device__ __forceinline__ void stage_row(float* sbuf, const float* gsrc, int lane) {
    uint32_t sa = (uint32_t)__cvta_generic_to_shared(sbuf + lane * 4);
    const float* g = gsrc + lane * 4;
    cp_async16(sa,        g);
    cp_async16(sa + 512,  g + 128);
    cp_async16(sa + 1024, g + 256);
    cp_async16(sa + 1536, g + 384);
}

// ---------------------------------------------------------------------------
// bitonic clean of a register-resident 16-array (bitonic -> sorted ascending)
// ---------------------------------------------------------------------------
__device__ __forceinline__ void bitonic_clean16(float* r) {
#pragma unroll
    for (int j = 8; j > 0; j >>= 1) {
#pragma unroll
        for (int i = 0; i < TOPK; ++i) {
            if ((i & j) == 0 && (i ^ j) > i) {
                float lo = fminf(r[i], r[i ^ j]);
                float hi = fmaxf(r[i], r[i ^ j]);
                r[i] = lo; r[i ^ j] = hi;
            }
        }
    }
}

// merge own sorted-16 with XOR-partner lane's sorted-16; all lanes end with
// the sorted 16 smallest of the union. Branchless.
__device__ __forceinline__ void shfl_merge16(float* r, int off) {
#pragma unroll
    for (int i = 0; i < 8; ++i) {
        float ohi = __shfl_xor_sync(0xFFFFFFFFu, r[15 - i], off);
        float olo = __shfl_xor_sync(0xFFFFFFFFu, r[i], off);
        r[i]      = fminf(r[i], ohi);
        r[15 - i] = fminf(r[15 - i], olo);
    }
    bitonic_clean16(r);
}

__device__ __forceinline__ float l1_partial(float4 v, float4 e) {
    return fabsf(v.x - e.x) + fabsf(v.y - e.y) + fabsf(v.z - e.z) + fabsf(v.w - e.w);
}

// ---------------------------------------------------------------------------
// Kernel 1: fused GEMV. 64 blocks x 512 threads; last block finishes.
// ---------------------------------------------------------------------------
__global__ void enc_kernel(const float* __restrict__ data,
                           const float* __restrict__ mean,
                           const float* __restrict__ stdv,
                           const float* __restrict__ W,
                           const float* __restrict__ b) {
    __shared__ float xn[ROWS_PER_PART];
    __shared__ unsigned int s_ticket;

    int t = threadIdx.x;              // output column
    int r0 = blockIdx.x * ROWS_PER_PART;
    if (t < ROWS_PER_PART) {
        int r = r0 + t;
        float s = stdv[r];
        xn[t] = (s == 0.0f) ? 0.0f : (data[r] - mean[r]) / s;
    }
    __syncthreads();
    float acc = 0.0f;
#pragma unroll
    for (int i = 0; i < ROWS_PER_PART; ++i)
        acc = fmaf(xn[i], W[(size_t)(r0 + i) * OUT_DIM + t], acc);
    g_part[blockIdx.x * OUT_DIM + t] = acc;

    __threadfence();
    __syncthreads();
    if (t == 0) s_ticket = atomicAdd(&g_ctr_enc, 1u);
    __syncthreads();
    if (s_ticket == ENC_PARTS - 1) {
        __threadfence();
        float sum = b[t];
#pragma unroll
        for (int p = 0; p < ENC_PARTS; ++p)
            sum += g_part[p * OUT_DIM + t];
        g_enc[t] = tanhf(sum);
        __threadfence();
        __syncthreads();
        if (t == 0) g_ctr_enc = 0u;
    }
}

// ---------------------------------------------------------------------------
// Kernel 2: cp.async double-buffered dist. Each warp streams its strided
// rows through a private 2x2KB smem buffer; compute reads smem (29 cyc),
// DRAM stays saturated with one full row in flight per warp at all times.
// 456 blocks x 512 thr, 3 blocks/SM, one full-chip wave.
// ---------------------------------------------------------------------------
__global__ void __launch_bounds__(DIST_NT, 3)
dist_topk_kernel(const float* __restrict__ memory,
                 const float* __restrict__ exp_w,
                 float* __restrict__ out) {
    extern __shared__ float sbuf[];          // [16 warps][2][512 floats]
    __shared__ float se[OUT_DIM];
    __shared__ float swarp[WARPS_PER_BLOCK * TOPK];
    __shared__ unsigned int s_ticket;

    int t = threadIdx.x;
    se[t] = g_enc[t];
    __syncthreads();

    int warp = t >> 5;
    int lane = t & 31;
    int gw   = blockIdx.x * WARPS_PER_BLOCK + warp;    // 0..7295
    int nrows = ROWS_BASE + (gw < ROWS_REM ? 1 : 0);   // 17 or 18

    const float4* es = (const float4*)se;
    float4 e0 = es[0 * 32 + lane];
    float4 e1 = es[1 * 32 + lane];
    float4 e2 = es[2 * 32 + lane];
    float4 e3 = es[3 * 32 + lane];

    float* buf0 = sbuf + warp * (2 * OUT_DIM);
    float* buf1 = buf0 + OUT_DIM;

    float my = FLT_MAX;   // lane k holds dist of this warp's k-th row

    // prologue: stage rows 0 and 1 (nrows >= 17, both exist)
    stage_row(buf0, memory + (size_t)gw * OUT_DIM, lane);
    CP_COMMIT();
    stage_row(buf1, memory + ((size_t)gw + NWARPS) * OUT_DIM, lane);
    CP_COMMIT();

    for (int k = 0; k < nrows; ++k) {
        CP_WAIT1();                      // group k complete (row k in smem)
        __syncwarp();
        float* b = (k & 1) ? buf1 : buf0;
        const float4* b4 = (const float4*)b;
        float4 v0 = b4[0 * 32 + lane];
        float4 v1 = b4[1 * 32 + lane];
        float4 v2 = b4[2 * 32 + lane];
        float4 v3 = b4[3 * 32 + lane];

        float p0 = l1_partial(v0, e0);
        float p1 = l1_partial(v1, e1);
        float p2 = l1_partial(v2, e2);
        float p3 = l1_partial(v3, e3);
        float s = (p0 + p1) + (p2 + p3);

#pragma unroll
        for (int o = 16; o > 0; o >>= 1)
            s += __shfl_xor_sync(0xFFFFFFFFu, s, o);

        my = (lane == k) ? s : my;

        // refill the buffer just consumed with row k+2 (if any), then commit
        // (empty commit keeps group accounting aligned with k)
        if (k + 2 < nrows)
            stage_row(b, memory + ((size_t)gw + (size_t)(k + 2) * NWARPS) * OUT_DIM, lane);
        CP_COMMIT();
    }

    // warp bitonic sort over 32 lane values (<=18 valid + FLT_MAX pad), asc
#pragma unroll
    for (int k = 2; k <= 32; k <<= 1) {
#pragma unroll
        for (int j = k >> 1; j > 0; j >>= 1) {
            float other = __shfl_xor_sync(0xFFFFFFFFu, my, j);
            bool up = ((lane & k) == 0);
            bool lower = ((lane & j) == 0);
            my = (lower == up) ? fminf(my, other) : fmaxf(my, other);
        }
    }
    if (lane < TOPK) swarp[warp * TOPK + lane] = my;
    __syncthreads();

    // warp 0 merges the 16 per-warp lists -> block's sorted top-16
    if (warp == 0) {
        float r[TOPK];
#pragma unroll
        for (int i = 0; i < TOPK; ++i)
            r[i] = (lane < 16) ? swarp[lane * TOPK + i] : FLT_MAX;
        shfl_merge16(r, 16);
        shfl_merge16(r, 8);
        shfl_merge16(r, 4);
        shfl_merge16(r, 2);
        shfl_merge16(r, 1);
        if (lane == 0) {
            float4* o4 = (float4*)(g_cand + blockIdx.x * TOPK);
            o4[0] = make_float4(r[0], r[1], r[2], r[3]);
            o4[1] = make_float4(r[4], r[5], r[6], r[7]);
            o4[2] = make_float4(r[8], r[9], r[10], r[11]);
            o4[3] = make_float4(r[12], r[13], r[14], r[15]);
        }
    }

    // ---- last-block-done: merge 456 sorted 16-lists + loss ----
    __threadfence();
    __syncthreads();
    if (t == 0) s_ticket = atomicAdd(&g_ctr_dist, 1u);
    __syncthreads();
    if (s_ticket != DIST_BLOCKS - 1) return;
    __threadfence();

    float r[TOPK];
    if (t < CAND_LISTS) {
        const float4* c4 = (const float4*)(g_cand + t * TOPK);
        float4 a = c4[0], bq = c4[1], c = c4[2], d = c4[3];
        r[0]=a.x;  r[1]=a.y;  r[2]=a.z;  r[3]=a.w;
        r[4]=bq.x; r[5]=bq.y; r[6]=bq.z; r[7]=bq.w;
        r[8]=c.x;  r[9]=c.y;  r[10]=c.z; r[11]=c.w;
        r[12]=d.x; r[13]=d.y; r[14]=d.z; r[15]=d.w;
    } else {
#pragma unroll
        for (int i = 0; i < TOPK; ++i) r[i] = FLT_MAX;
    }

    // in-warp 32 -> 1, then 16 warp lists -> 1
    shfl_merge16(r, 16);
    shfl_merge16(r, 8);
    shfl_merge16(r, 4);
    shfl_merge16(r, 2);
    shfl_merge16(r, 1);
    if (lane == 0) {
#pragma unroll
        for (int i = 0; i < TOPK; ++i) swarp[warp * TOPK + i] = r[i];
    }
    __syncthreads();
    if (warp == 0) {
#pragma unroll
        for (int i = 0; i < TOPK; ++i)
            r[i] = (lane < 16) ? swarp[lane * TOPK + i] : FLT_MAX;
        shfl_merge16(r, 16);
        shfl_merge16(r, 8);
        shfl_merge16(r, 4);
        shfl_merge16(r, 2);
        shfl_merge16(r, 1);
        if (lane == 0) {
            float num = 0.0f, den = 0.0f;
#pragma unroll
            for (int i = 0; i < TOPK; ++i) {
                float w = exp_w[i];
                num = fmaf(r[i], w, num);
                den += w;
            }
            out[0] = num / den;
            g_ctr_dist = 0u;
        }
    }
}

// ---------------------------------------------------------------------------
// Launch.
// Inputs: data[256], mean[256], std[256], memory[131072*512],
//         W[256*512], b[512], exp_w[16]  ->  out[1] float
// ---------------------------------------------------------------------------
extern "C" void kernel_launch(void* const* d_in, const int* in_sizes, int n_in,
                              void* d_out, int out_size) {
    const float* data   = (const float*)d_in[0];
    const float* mean   = (const float*)d_in[1];
    const float* stdv   = (const float*)d_in[2];
    const float* memory = (const float*)d_in[3];
    const float* W      = (const float*)d_in[4];
    const float* b      = (const float*)d_in[5];
    const float* exp_w  = (const float*)d_in[6];
    float* out = (float*)d_out;

    static int smem_set = 0;
    if (!smem_set) {
        cudaFuncSetAttribute(dist_topk_kernel,
                             cudaFuncAttributeMaxDynamicSharedMemorySize,
                             BUF_SMEM);
        smem_set = 1;
    }

    enc_kernel<<<ENC_PARTS, OUT_DIM>>>(data, mean, stdv, W, b);
    dist_topk_kernel<<<DIST_BLOCKS, DIST_NT, BUF_SMEM>>>(memory, exp_w, out);
}

// round 14
// speedup vs baseline: 1.0499x; 1.0499x over previous
#include <cuda_runtime.h>
#include <float.h>

#define IN_DIM 256
#define OUT_DIM 512
#define MEM_LEN 131072
#define TOPK 16

#define ENC_PARTS 64
#define ROWS_PER_PART (IN_DIM / ENC_PARTS)   // 4

#define DIST_BLOCKS 608                       // 152 SMs * 4 blocks = ONE wave
#define DIST_NT 512                           // 16 warps
#define WARPS_PER_BLOCK (DIST_NT / 32)
#define NWARPS (DIST_BLOCKS * WARPS_PER_BLOCK) // 9728 warps
#define ROWS_BASE (MEM_LEN / NWARPS)          // 13
#define ROWS_REM  (MEM_LEN % NWARPS)          // 4608 warps do 14

#define CAND_LISTS DIST_BLOCKS                // 608 sorted 16-lists
#define CAND_N (CAND_LISTS * TOPK)

__device__ float g_enc[OUT_DIM];
__device__ float g_part[ENC_PARTS * OUT_DIM];
__device__ float g_cand[CAND_N];
__device__ volatile unsigned int g_bar1;
__device__ volatile unsigned int g_bar2;
__device__ unsigned int g_ctr_dist;

// ---------------------------------------------------------------------------
// grid barrier: safe because grid == exactly one resident wave (608 blocks,
// 4/SM on 152 SMs, regs capped at 32 by __launch_bounds__).
// ---------------------------------------------------------------------------
__device__ __forceinline__ void grid_barrier(volatile unsigned int* bar, int t) {
    __syncthreads();
    if (t == 0) {
        __threadfence();                       // publish my writes
        atomicAdd((unsigned int*)bar, 1u);
        while (*bar < DIST_BLOCKS) __nanosleep(64);
    }
    __syncthreads();
    __threadfence();                           // see others' writes
}

// ---------------------------------------------------------------------------
// bitonic clean of a register-resident 16-array (bitonic -> sorted ascending)
// ---------------------------------------------------------------------------
__device__ __forceinline__ void bitonic_clean16(float* r) {
#pragma unroll
    for (int j = 8; j > 0; j >>= 1) {
#pragma unroll
        for (int i = 0; i < TOPK; ++i) {
            if ((i & j) == 0 && (i ^ j) > i) {
                float lo = fminf(r[i], r[i ^ j]);
                float hi = fmaxf(r[i], r[i ^ j]);
                r[i] = lo; r[i ^ j] = hi;
            }
        }
    }
}

// merge own sorted-16 with register list b (sorted): keep 16 smallest, sorted
__device__ __forceinline__ void reg_merge16(float* r, const float* b) {
#pragma unroll
    for (int i = 0; i < TOPK; ++i) r[i] = fminf(r[i], b[TOPK - 1 - i]);
    bitonic_clean16(r);
}

// merge own sorted-16 with XOR-partner lane's sorted-16; all lanes end with
// the sorted 16 smallest of the union. Branchless.
__device__ __forceinline__ void shfl_merge16(float* r, int off) {
#pragma unroll
    for (int i = 0; i < 8; ++i) {
        float ohi = __shfl_xor_sync(0xFFFFFFFFu, r[15 - i], off);
        float olo = __shfl_xor_sync(0xFFFFFFFFu, r[i], off);
        r[i]      = fminf(r[i], ohi);
        r[15 - i] = fminf(r[15 - i], olo);
    }
    bitonic_clean16(r);
}

// ---------------------------------------------------------------------------
// Single fused kernel: enc partials -> barrier -> enc finish -> barrier ->
// dist (verbatim R7 loop) -> warp/block top-16 -> last-block global merge.
// ---------------------------------------------------------------------------
__global__ void __launch_bounds__(DIST_NT, 4)
fused_kernel(const float* __restrict__ data,
             const float* __restrict__ mean,
             const float* __restrict__ stdv,
             const float* __restrict__ W,
             const float* __restrict__ b,
             const float* __restrict__ memory,
             const float* __restrict__ exp_w,
             float* __restrict__ out) {
    __shared__ float se[OUT_DIM];
    __shared__ float xn[ROWS_PER_PART];
    __shared__ float swarp[WARPS_PER_BLOCK * TOPK];
    __shared__ unsigned int s_ticket;

    int t = threadIdx.x;

    // ---- Phase A: GEMV partials on blocks 0..63 ----
    if (blockIdx.x < ENC_PARTS) {
        int r0 = blockIdx.x * ROWS_PER_PART;
        if (t < ROWS_PER_PART) {
            int r = r0 + t;
            float s = stdv[r];
            xn[t] = (s == 0.0f) ? 0.0f : (data[r] - mean[r]) / s;
        }
        __syncthreads();
        float acc = 0.0f;
#pragma unroll
        for (int i = 0; i < ROWS_PER_PART; ++i)
            acc = fmaf(xn[i], W[(size_t)(r0 + i) * OUT_DIM + t], acc);
        g_part[blockIdx.x * OUT_DIM + t] = acc;
    }

    grid_barrier(&g_bar1, t);

    // ---- Phase B: finish enc on block 0 ----
    if (blockIdx.x == 0) {
        float sum = b[t];
#pragma unroll
        for (int p = 0; p < ENC_PARTS; ++p)
            sum += g_part[p * OUT_DIM + t];
        g_enc[t] = tanhf(sum);
    }

    grid_barrier(&g_bar2, t);

    // ---- Phase C: dist (R7 verbatim) ----
    se[t] = g_enc[t];
    __syncthreads();

    int warp = t >> 5;
    int lane = t & 31;
    int gw   = blockIdx.x * WARPS_PER_BLOCK + warp;    // global warp id
    int nrows = ROWS_BASE + (gw < ROWS_REM ? 1 : 0);   // 13 or 14

    const float4* es = (const float4*)se;
    float my = FLT_MAX;   // lane k holds dist of this warp's k-th row

    for (int k = 0; k < nrows; ++k) {
        size_t row = (size_t)gw + (size_t)k * NWARPS;
        const float4* m = (const float4*)(memory + row * OUT_DIM);
        float4 v0 = __ldg(&m[0 * 32 + lane]);
        float4 v1 = __ldg(&m[1 * 32 + lane]);
        float4 v2 = __ldg(&m[2 * 32 + lane]);
        float4 v3 = __ldg(&m[3 * 32 + lane]);

        float4 e0 = es[0 * 32 + lane];
        float4 e1 = es[1 * 32 + lane];
        float4 e2 = es[2 * 32 + lane];
        float4 e3 = es[3 * 32 + lane];

        float s = 0.0f;
        s += fabsf(v0.x - e0.x) + fabsf(v0.y - e0.y) + fabsf(v0.z - e0.z) + fabsf(v0.w - e0.w);
        s += fabsf(v1.x - e1.x) + fabsf(v1.y - e1.y) + fabsf(v1.z - e1.z) + fabsf(v1.w - e1.w);
        s += fabsf(v2.x - e2.x) + fabsf(v2.y - e2.y) + fabsf(v2.z - e2.z) + fabsf(v2.w - e2.w);
        s += fabsf(v3.x - e3.x) + fabsf(v3.y - e3.y) + fabsf(v3.z - e3.z) + fabsf(v3.w - e3.w);

#pragma unroll
        for (int o = 16; o > 0; o >>= 1)
            s += __shfl_xor_sync(0xFFFFFFFFu, s, o);

        my = (lane == k) ? s : my;
    }

    // warp bitonic sort over 32 lane values (valid + FLT_MAX pad), ascending
#pragma unroll
    for (int k = 2; k <= 32; k <<= 1) {
#pragma unroll
        for (int j = k >> 1; j > 0; j >>= 1) {
            float other = __shfl_xor_sync(0xFFFFFFFFu, my, j);
            bool up = ((lane & k) == 0);
            bool lower = ((lane & j) == 0);
            my = (lower == up) ? fminf(my, other) : fmaxf(my, other);
        }
    }
    if (lane < TOPK) swarp[warp * TOPK + lane] = my;
    __syncthreads();

    // warp 0 merges the 16 per-warp lists -> block's sorted top-16
    if (warp == 0) {
        float r[TOPK];
#pragma unroll
        for (int i = 0; i < TOPK; ++i)
            r[i] = (lane < 16) ? swarp[lane * TOPK + i] : FLT_MAX;
        shfl_merge16(r, 16);
        shfl_merge16(r, 8);
        shfl_merge16(r, 4);
        shfl_merge16(r, 2);
        shfl_merge16(r, 1);
        if (lane == 0) {
            float4* o4 = (float4*)(g_cand + blockIdx.x * TOPK);
            o4[0] = make_float4(r[0], r[1], r[2], r[3]);
            o4[1] = make_float4(r[4], r[5], r[6], r[7]);
            o4[2] = make_float4(r[8], r[9], r[10], r[11]);
            o4[3] = make_float4(r[12], r[13], r[14], r[15]);
        }
    }

    // ---- last-block-done: merge 608 sorted 16-lists + loss ----
    __threadfence();
    __syncthreads();
    if (t == 0) s_ticket = atomicAdd(&g_ctr_dist, 1u);
    __syncthreads();
    if (s_ticket != DIST_BLOCKS - 1) return;
    __threadfence();

    float r[TOPK];
    {
        const float4* c4 = (const float4*)(g_cand + t * TOPK);
        float4 a = c4[0], bq = c4[1], c = c4[2], d = c4[3];
        r[0]=a.x;  r[1]=a.y;  r[2]=a.z;  r[3]=a.w;
        r[4]=bq.x; r[5]=bq.y; r[6]=bq.z; r[7]=bq.w;
        r[8]=c.x;  r[9]=c.y;  r[10]=c.z; r[11]=c.w;
        r[12]=d.x; r[13]=d.y; r[14]=d.z; r[15]=d.w;
    }
    // fold lists 512..607 into threads 0..95
    if (t < CAND_LISTS - DIST_NT) {
        float b2[TOPK];
        const float4* c4 = (const float4*)(g_cand + (DIST_NT + t) * TOPK);
        float4 a = c4[0], bq = c4[1], c = c4[2], d = c4[3];
        b2[0]=a.x;  b2[1]=a.y;  b2[2]=a.z;  b2[3]=a.w;
        b2[4]=bq.x; b2[5]=bq.y; b2[6]=bq.z; b2[7]=bq.w;
        b2[8]=c.x;  b2[9]=c.y;  b2[10]=c.z; b2[11]=c.w;
        b2[12]=d.x; b2[13]=d.y; b2[14]=d.z; b2[15]=d.w;
        reg_merge16(r, b2);
    }

    // in-warp 32 -> 1, then 16 warp lists -> 1
    shfl_merge16(r, 16);
    shfl_merge16(r, 8);
    shfl_merge16(r, 4);
    shfl_merge16(r, 2);
    shfl_merge16(r, 1);
    if (lane == 0) {
#pragma unroll
        for (int i = 0; i < TOPK; ++i) swarp[warp * TOPK + i] = r[i];
    }
    __syncthreads();
    if (warp == 0) {
#pragma unroll
        for (int i = 0; i < TOPK; ++i)
            r[i] = (lane < 16) ? swarp[lane * TOPK + i] : FLT_MAX;
        shfl_merge16(r, 16);
        shfl_merge16(r, 8);
        shfl_merge16(r, 4);
        shfl_merge16(r, 2);
        shfl_merge16(r, 1);
        if (lane == 0) {
            float num = 0.0f, den = 0.0f;
#pragma unroll
            for (int i = 0; i < TOPK; ++i) {
                float w = exp_w[i];
                num = fmaf(r[i], w, num);
                den += w;
            }
            out[0] = num / den;
            // reset all counters for the next graph replay (all other
            // blocks have passed their final atomicAdd, so no one is
            // still reading the barrier words)
            g_bar1 = 0u;
            g_bar2 = 0u;
            g_ctr_dist = 0u;
        }
    }
}

// ---------------------------------------------------------------------------
// Launch.
// Inputs: data[256], mean[256], std[256], memory[131072*512],
//         W[256*512], b[512], exp_w[16]  ->  out[1] float
// ---------------------------------------------------------------------------
extern "C" void kernel_launch(void* const* d_in, const int* in_sizes, int n_in,
                              void* d_out, int out_size) {
    const float* data   = (const float*)d_in[0];
    const float* mean   = (const float*)d_in[1];
    const float* stdv   = (const float*)d_in[2];
    const float* memory = (const float*)d_in[3];
    const float* W      = (const float*)d_in[4];
    const float* b      = (const float*)d_in[5];
    const float* exp_w  = (const float*)d_in[6];
    float* out = (float*)d_out;

    fused_kernel<<<DIST_BLOCKS, DIST_NT>>>(data, mean, stdv, W, b,
                                           memory, exp_w, out);
}

// round 15
// speedup vs baseline: 1.1071x; 1.0544x over previous
#include <cuda_runtime.h>
#include <float.h>

#define IN_DIM 256
#define OUT_DIM 512
#define MEM_LEN 131072
#define TOPK 16

#define ENC_PARTS 64
#define ROWS_PER_PART (IN_DIM / ENC_PARTS)   // 4

#define DIST_BLOCKS 608                       // 152 SMs * 4 blocks, one wave
#define DIST_NT 512                           // 16 warps
#define WARPS_PER_BLOCK (DIST_NT / 32)
#define NWARPS (DIST_BLOCKS * WARPS_PER_BLOCK) // 9728 warps
#define ROWS_BASE (MEM_LEN / NWARPS)          // 13
#define ROWS_REM  (MEM_LEN % NWARPS)          // 4608 warps do 14

#define CAND_LISTS DIST_BLOCKS                // 608 sorted 16-lists
#define CAND_N (CAND_LISTS * TOPK)

__device__ float g_enc_raw[OUT_DIM];          // zero-init; reset each replay
__device__ float g_cand[CAND_N];
__device__ unsigned int g_ctr_dist;

// ---------------------------------------------------------------------------
// bitonic clean of a register-resident 16-array (bitonic -> sorted ascending)
// ---------------------------------------------------------------------------
__device__ __forceinline__ void bitonic_clean16(float* r) {
#pragma unroll
    for (int j = 8; j > 0; j >>= 1) {
#pragma unroll
        for (int i = 0; i < TOPK; ++i) {
            if ((i & j) == 0 && (i ^ j) > i) {
                float lo = fminf(r[i], r[i ^ j]);
                float hi = fmaxf(r[i], r[i ^ j]);
                r[i] = lo; r[i ^ j] = hi;
            }
        }
    }
}

// merge own sorted-16 with register list b (sorted): keep 16 smallest, sorted
__device__ __forceinline__ void reg_merge16(float* r, const float* b) {
#pragma unroll
    for (int i = 0; i < TOPK; ++i) r[i] = fminf(r[i], b[TOPK - 1 - i]);
    bitonic_clean16(r);
}

// merge own sorted-16 with XOR-partner lane's sorted-16; all lanes end with
// the sorted 16 smallest of the union. Branchless.
__device__ __forceinline__ void shfl_merge16(float* r, int off) {
#pragma unroll
    for (int i = 0; i < 8; ++i) {
        float ohi = __shfl_xor_sync(0xFFFFFFFFu, r[15 - i], off);
        float olo = __shfl_xor_sync(0xFFFFFFFFu, r[i], off);
        r[i]      = fminf(r[i], ohi);
        r[15 - i] = fminf(r[15 - i], olo);
    }
    bitonic_clean16(r);
}

__device__ __forceinline__ void prefetch_l2(const void* p) {
    asm volatile("prefetch.global.L2 [%0];" :: "l"(p));
}

// ---------------------------------------------------------------------------
// Kernel 1: GEMV partials via float atomicAdd (no finisher phase), plus
// L2 warmup: blocks 64..607 prefetch the first two dist rows for their
// corresponding dist warps while the GEMV blocks work.
// ---------------------------------------------------------------------------
__global__ void __launch_bounds__(DIST_NT, 4)
enc_kernel(const float* __restrict__ data,
           const float* __restrict__ mean,
           const float* __restrict__ stdv,
           const float* __restrict__ W,
           const float* __restrict__ memory) {
    __shared__ float xn[ROWS_PER_PART];
    int t = threadIdx.x;

    if (blockIdx.x < ENC_PARTS) {
        int r0 = blockIdx.x * ROWS_PER_PART;
        if (t < ROWS_PER_PART) {
            int r = r0 + t;
            float s = stdv[r];
            xn[t] = (s == 0.0f) ? 0.0f : (data[r] - mean[r]) / s;
        }
        __syncthreads();
        float acc = 0.0f;
#pragma unroll
        for (int i = 0; i < ROWS_PER_PART; ++i)
            acc = fmaf(xn[i], W[(size_t)(r0 + i) * OUT_DIM + t], acc);
        atomicAdd(&g_enc_raw[t], acc);
    } else {
        // warm L2 with the first two rows of this block's dist warps
        int warp = t >> 5;
        int lane = t & 31;
        int gw = blockIdx.x * WARPS_PER_BLOCK + warp;
        const float4* m0 = (const float4*)(memory + (size_t)gw * OUT_DIM);
        const float4* m1 = (const float4*)(memory + ((size_t)gw + NWARPS) * OUT_DIM);
        prefetch_l2(&m0[0 * 32 + lane]);
        prefetch_l2(&m0[1 * 32 + lane]);
        prefetch_l2(&m0[2 * 32 + lane]);
        prefetch_l2(&m0[3 * 32 + lane]);
        prefetch_l2(&m1[0 * 32 + lane]);
        prefetch_l2(&m1[1 * 32 + lane]);
        prefetch_l2(&m1[2 * 32 + lane]);
        prefetch_l2(&m1[3 * 32 + lane]);
    }
}

// ---------------------------------------------------------------------------
// Kernel 2 (R7 verbatim dist loop): bias+tanh folded into the smem fill,
// per-warp strided rows, warp top-16, block merge, last-block global merge.
// 608 blocks x 512 thr, <=32 regs -> 4 blocks/SM, one full-chip wave.
// ---------------------------------------------------------------------------
__global__ void __launch_bounds__(DIST_NT, 4)
dist_topk_kernel(const float* __restrict__ memory,
                 const float* __restrict__ b,
                 const float* __restrict__ exp_w,
                 float* __restrict__ out) {
    __shared__ float se[OUT_DIM];
    __shared__ float swarp[WARPS_PER_BLOCK * TOPK];
    __shared__ unsigned int s_ticket;

    int t = threadIdx.x;
    se[t] = tanhf(g_enc_raw[t] + b[t]);     // bias + tanh folded here
    __syncthreads();

    int warp = t >> 5;
    int lane = t & 31;
    int gw   = blockIdx.x * WARPS_PER_BLOCK + warp;    // global warp id
    int nrows = ROWS_BASE + (gw < ROWS_REM ? 1 : 0);   // 13 or 14

    const float4* es = (const float4*)se;
    float my = FLT_MAX;   // lane k holds dist of this warp's k-th row

    for (int k = 0; k < nrows; ++k) {
        size_t row = (size_t)gw + (size_t)k * NWARPS;
        const float4* m = (const float4*)(memory + row * OUT_DIM);
        float4 v0 = __ldg(&m[0 * 32 + lane]);
        float4 v1 = __ldg(&m[1 * 32 + lane]);
        float4 v2 = __ldg(&m[2 * 32 + lane]);
        float4 v3 = __ldg(&m[3 * 32 + lane]);

        float4 e0 = es[0 * 32 + lane];
        float4 e1 = es[1 * 32 + lane];
        float4 e2 = es[2 * 32 + lane];
        float4 e3 = es[3 * 32 + lane];

        float s = 0.0f;
        s += fabsf(v0.x - e0.x) + fabsf(v0.y - e0.y) + fabsf(v0.z - e0.z) + fabsf(v0.w - e0.w);
        s += fabsf(v1.x - e1.x) + fabsf(v1.y - e1.y) + fabsf(v1.z - e1.z) + fabsf(v1.w - e1.w);
        s += fabsf(v2.x - e2.x) + fabsf(v2.y - e2.y) + fabsf(v2.z - e2.z) + fabsf(v2.w - e2.w);
        s += fabsf(v3.x - e3.x) + fabsf(v3.y - e3.y) + fabsf(v3.z - e3.z) + fabsf(v3.w - e3.w);

#pragma unroll
        for (int o = 16; o > 0; o >>= 1)
            s += __shfl_xor_sync(0xFFFFFFFFu, s, o);

        my = (lane == k) ? s : my;
    }

    // warp bitonic sort over 32 lane values (valid + FLT_MAX pad), ascending
#pragma unroll
    for (int k = 2; k <= 32; k <<= 1) {
#pragma unroll
        for (int j = k >> 1; j > 0; j >>= 1) {
            float other = __shfl_xor_sync(0xFFFFFFFFu, my, j);
            bool up = ((lane & k) == 0);
            bool lower = ((lane & j) == 0);
            my = (lower == up) ? fminf(my, other) : fmaxf(my, other);
        }
    }
    if (lane < TOPK) swarp[warp * TOPK + lane] = my;
    __syncthreads();

    // warp 0 merges the 16 per-warp lists -> block's sorted top-16
    if (warp == 0) {
        float r[TOPK];
#pragma unroll
        for (int i = 0; i < TOPK; ++i)
            r[i] = (lane < 16) ? swarp[lane * TOPK + i] : FLT_MAX;
        shfl_merge16(r, 16);
        shfl_merge16(r, 8);
        shfl_merge16(r, 4);
        shfl_merge16(r, 2);
        shfl_merge16(r, 1);
        if (lane == 0) {
            float4* o4 = (float4*)(g_cand + blockIdx.x * TOPK);
            o4[0] = make_float4(r[0], r[1], r[2], r[3]);
            o4[1] = make_float4(r[4], r[5], r[6], r[7]);
            o4[2] = make_float4(r[8], r[9], r[10], r[11]);
            o4[3] = make_float4(r[12], r[13], r[14], r[15]);
        }
    }

    // ---- last-block-done: merge 608 sorted 16-lists + loss ----
    __threadfence();
    __syncthreads();
    if (t == 0) s_ticket = atomicAdd(&g_ctr_dist, 1u);
    __syncthreads();
    if (s_ticket != DIST_BLOCKS - 1) return;
    __threadfence();

    float r[TOPK];
    {
        const float4* c4 = (const float4*)(g_cand + t * TOPK);
        float4 a = c4[0], bq = c4[1], c = c4[2], d = c4[3];
        r[0]=a.x;  r[1]=a.y;  r[2]=a.z;  r[3]=a.w;
        r[4]=bq.x; r[5]=bq.y; r[6]=bq.z; r[7]=bq.w;
        r[8]=c.x;  r[9]=c.y;  r[10]=c.z; r[11]=c.w;
        r[12]=d.x; r[13]=d.y; r[14]=d.z; r[15]=d.w;
    }
    // fold lists 512..607 into threads 0..95
    if (t < CAND_LISTS - DIST_NT) {
        float b2[TOPK];
        const float4* c4 = (const float4*)(g_cand + (DIST_NT + t) * TOPK);
        float4 a = c4[0], bq = c4[1], c = c4[2], d = c4[3];
        b2[0]=a.x;  b2[1]=a.y;  b2[2]=a.z;  b2[3]=a.w;
        b2[4]=bq.x; b2[5]=bq.y; b2[6]=bq.z; b2[7]=bq.w;
        b2[8]=c.x;  b2[9]=c.y;  b2[10]=c.z; b2[11]=c.w;
        b2[12]=d.x; b2[13]=d.y; b2[14]=d.z; b2[15]=d.w;
        reg_merge16(r, b2);
    }

    // in-warp 32 -> 1, then 16 warp lists -> 1
    shfl_merge16(r, 16);
    shfl_merge16(r, 8);
    shfl_merge16(r, 4);
    shfl_merge16(r, 2);
    shfl_merge16(r, 1);
    if (lane == 0) {
#pragma unroll
        for (int i = 0; i < TOPK; ++i) swarp[warp * TOPK + i] = r[i];
    }
    __syncthreads();
    if (warp == 0) {
#pragma unroll
        for (int i = 0; i < TOPK; ++i)
            r[i] = (lane < 16) ? swarp[lane * TOPK + i] : FLT_MAX;
        shfl_merge16(r, 16);
        shfl_merge16(r, 8);
        shfl_merge16(r, 4);
        shfl_merge16(r, 2);
        shfl_merge16(r, 1);
        if (lane == 0) {
            float num = 0.0f, den = 0.0f;
#pragma unroll
            for (int i = 0; i < TOPK; ++i) {
                float w = exp_w[i];
                num = fmaf(r[i], w, num);
                den += w;
            }
            out[0] = num / den;
            g_ctr_dist = 0u;
        }
    }
    // reset accumulator for the next graph replay (all blocks have long
    // since read g_enc_raw at their kernel start)
    g_enc_raw[t] = 0.0f;
}

// ---------------------------------------------------------------------------
// Launch.
// Inputs: data[256], mean[256], std[256], memory[131072*512],
//         W[256*512], b[512], exp_w[16]  ->  out[1] float
// ---------------------------------------------------------------------------
extern "C" void kernel_launch(void* const* d_in, const int* in_sizes, int n_in,
                              void* d_out, int out_size) {
    const float* data   = (const float*)d_in[0];
    const float* mean   = (const float*)d_in[1];
    const float* stdv   = (const float*)d_in[2];
    const float* memory = (const float*)d_in[3];
    const float* W      = (const float*)d_in[4];
    const float* b      = (const float*)d_in[5];
    const float* exp_w  = (const float*)d_in[6];
    float* out = (float*)d_out;

    enc_kernel<<<DIST_BLOCKS, DIST_NT>>>(data, mean, stdv, W, memory);
    dist_topk_kernel<<<DIST_BLOCKS, DIST_NT>>>(memory, b, exp_w, out);
}

// round 16
// speedup vs baseline: 1.1084x; 1.0012x over previous
#include <cuda_runtime.h>
#include <float.h>

#define IN_DIM 256
#define OUT_DIM 512
#define MEM_LEN 131072
#define TOPK 16

#define ENC_PARTS 64
#define ROWS_PER_PART (IN_DIM / ENC_PARTS)   // 4

#define DIST_BLOCKS 608                       // 152 SMs * 4 blocks, one wave
#define DIST_NT 512                           // 16 warps
#define WARPS_PER_BLOCK (DIST_NT / 32)
#define NWARPS (DIST_BLOCKS * WARPS_PER_BLOCK) // 9728 warps
#define ROWS_BASE (MEM_LEN / NWARPS)          // 13
#define ROWS_REM  (MEM_LEN % NWARPS)          // 4608 warps do 14

#define CAND_LISTS DIST_BLOCKS                // 608 sorted 16-lists
#define CAND_N (CAND_LISTS * TOPK)

__device__ float g_enc_raw[OUT_DIM];          // zero-init; reset each replay
__device__ float g_cand[CAND_N];
__device__ unsigned int g_ctr_dist;

// ---------------------------------------------------------------------------
// bitonic clean of a register-resident 16-array (bitonic -> sorted ascending)
// ---------------------------------------------------------------------------
__device__ __forceinline__ void bitonic_clean16(float* r) {
#pragma unroll
    for (int j = 8; j > 0; j >>= 1) {
#pragma unroll
        for (int i = 0; i < TOPK; ++i) {
            if ((i & j) == 0 && (i ^ j) > i) {
                float lo = fminf(r[i], r[i ^ j]);
                float hi = fmaxf(r[i], r[i ^ j]);
                r[i] = lo; r[i ^ j] = hi;
            }
        }
    }
}

// merge own sorted-16 with register list b (sorted): keep 16 smallest, sorted
__device__ __forceinline__ void reg_merge16(float* r, const float* b) {
#pragma unroll
    for (int i = 0; i < TOPK; ++i) r[i] = fminf(r[i], b[TOPK - 1 - i]);
    bitonic_clean16(r);
}

// merge own sorted-16 with XOR-partner lane's sorted-16; all lanes end with
// the sorted 16 smallest of the union. Branchless.
__device__ __forceinline__ void shfl_merge16(float* r, int off) {
#pragma unroll
    for (int i = 0; i < 8; ++i) {
        float ohi = __shfl_xor_sync(0xFFFFFFFFu, r[15 - i], off);
        float olo = __shfl_xor_sync(0xFFFFFFFFu, r[i], off);
        r[i]      = fminf(r[i], ohi);
        r[15 - i] = fminf(r[15 - i], olo);
    }
    bitonic_clean16(r);
}

__device__ __forceinline__ void prefetch_l2(const void* p) {
    asm volatile("prefetch.global.L2 [%0];" :: "l"(p));
}

// ---------------------------------------------------------------------------
// Kernel 1: GEMV partials via float atomicAdd. Triggers PDL completion at
// entry so the dist kernel's grid can launch and prefetch concurrently.
// ---------------------------------------------------------------------------
__global__ void __launch_bounds__(OUT_DIM, 4)
enc_kernel(const float* __restrict__ data,
           const float* __restrict__ mean,
           const float* __restrict__ stdv,
           const float* __restrict__ W) {
    cudaTriggerProgrammaticLaunchCompletion();

    __shared__ float xn[ROWS_PER_PART];
    int t = threadIdx.x;
    int r0 = blockIdx.x * ROWS_PER_PART;
    if (t < ROWS_PER_PART) {
        int r = r0 + t;
        float s = stdv[r];
        xn[t] = (s == 0.0f) ? 0.0f : (data[r] - mean[r]) / s;
    }
    __syncthreads();
    float acc = 0.0f;
#pragma unroll
    for (int i = 0; i < ROWS_PER_PART; ++i)
        acc = fmaf(xn[i], W[(size_t)(r0 + i) * OUT_DIM + t], acc);
    atomicAdd(&g_enc_raw[t], acc);
}

// ---------------------------------------------------------------------------
// Kernel 2 (PDL secondary): prefetch first two rows, THEN wait for enc via
// cudaGridDependencySynchronize, then the R7-verbatim dist loop, warp top-16,
// block merge, last-block global merge & loss. 608 x 512, 4/SM, one wave.
// ---------------------------------------------------------------------------
__global__ void __launch_bounds__(DIST_NT, 4)
dist_topk_kernel(const float* __restrict__ memory,
                 const float* __restrict__ b,
                 const float* __restrict__ exp_w,
                 float* __restrict__ out) {
    __shared__ float se[OUT_DIM];
    __shared__ float swarp[WARPS_PER_BLOCK * TOPK];
    __shared__ unsigned int s_ticket;

    int t = threadIdx.x;
    int warp = t >> 5;
    int lane = t & 31;
    int gw   = blockIdx.x * WARPS_PER_BLOCK + warp;    // global warp id

    // warm L2 with this warp's first two rows while enc still runs
    {
        const float4* m0 = (const float4*)(memory + (size_t)gw * OUT_DIM);
        const float4* m1 = (const float4*)(memory + ((size_t)gw + NWARPS) * OUT_DIM);
        prefetch_l2(&m0[0 * 32 + lane]);
        prefetch_l2(&m0[1 * 32 + lane]);
        prefetch_l2(&m0[2 * 32 + lane]);
        prefetch_l2(&m0[3 * 32 + lane]);
        prefetch_l2(&m1[0 * 32 + lane]);
        prefetch_l2(&m1[1 * 32 + lane]);
        prefetch_l2(&m1[2 * 32 + lane]);
        prefetch_l2(&m1[3 * 32 + lane]);
    }

    // wait for enc kernel's atomicAdds to be complete & visible
    cudaGridDependencySynchronize();

    se[t] = tanhf(g_enc_raw[t] + b[t]);     // bias + tanh folded here
    __syncthreads();

    int nrows = ROWS_BASE + (gw < ROWS_REM ? 1 : 0);   // 13 or 14

    const float4* es = (const float4*)se;
    float my = FLT_MAX;   // lane k holds dist of this warp's k-th row

    for (int k = 0; k < nrows; ++k) {
        size_t row = (size_t)gw + (size_t)k * NWARPS;
        const float4* m = (const float4*)(memory + row * OUT_DIM);
        float4 v0 = __ldg(&m[0 * 32 + lane]);
        float4 v1 = __ldg(&m[1 * 32 + lane]);
        float4 v2 = __ldg(&m[2 * 32 + lane]);
        float4 v3 = __ldg(&m[3 * 32 + lane]);

        float4 e0 = es[0 * 32 + lane];
        float4 e1 = es[1 * 32 + lane];
        float4 e2 = es[2 * 32 + lane];
        float4 e3 = es[3 * 32 + lane];

        float s = 0.0f;
        s += fabsf(v0.x - e0.x) + fabsf(v0.y - e0.y) + fabsf(v0.z - e0.z) + fabsf(v0.w - e0.w);
        s += fabsf(v1.x - e1.x) + fabsf(v1.y - e1.y) + fabsf(v1.z - e1.z) + fabsf(v1.w - e1.w);
        s += fabsf(v2.x - e2.x) + fabsf(v2.y - e2.y) + fabsf(v2.z - e2.z) + fabsf(v2.w - e2.w);
        s += fabsf(v3.x - e3.x) + fabsf(v3.y - e3.y) + fabsf(v3.z - e3.z) + fabsf(v3.w - e3.w);

#pragma unroll
        for (int o = 16; o > 0; o >>= 1)
            s += __shfl_xor_sync(0xFFFFFFFFu, s, o);

        my = (lane == k) ? s : my;
    }

    // warp bitonic sort over 32 lane values (valid + FLT_MAX pad), ascending
#pragma unroll
    for (int k = 2; k <= 32; k <<= 1) {
#pragma unroll
        for (int j = k >> 1; j > 0; j >>= 1) {
            float other = __shfl_xor_sync(0xFFFFFFFFu, my, j);
            bool up = ((lane & k) == 0);
            bool lower = ((lane & j) == 0);
            my = (lower == up) ? fminf(my, other) : fmaxf(my, other);
        }
    }
    if (lane < TOPK) swarp[warp * TOPK + lane] = my;
    __syncthreads();

    // warp 0 merges the 16 per-warp lists -> block's sorted top-16
    if (warp == 0) {
        float r[TOPK];
#pragma unroll
        for (int i = 0; i < TOPK; ++i)
            r[i] = (lane < 16) ? swarp[lane * TOPK + i] : FLT_MAX;
        shfl_merge16(r, 16);
        shfl_merge16(r, 8);
        shfl_merge16(r, 4);
        shfl_merge16(r, 2);
        shfl_merge16(r, 1);
        if (lane == 0) {
            float4* o4 = (float4*)(g_cand + blockIdx.x * TOPK);
            o4[0] = make_float4(r[0], r[1], r[2], r[3]);
            o4[1] = make_float4(r[4], r[5], r[6], r[7]);
            o4[2] = make_float4(r[8], r[9], r[10], r[11]);
            o4[3] = make_float4(r[12], r[13], r[14], r[15]);
        }
    }

    // ---- last-block-done: merge 608 sorted 16-lists + loss ----
    __threadfence();
    __syncthreads();
    if (t == 0) s_ticket = atomicAdd(&g_ctr_dist, 1u);
    __syncthreads();
    if (s_ticket != DIST_BLOCKS - 1) return;
    __threadfence();

    float r[TOPK];
    {
        const float4* c4 = (const float4*)(g_cand + t * TOPK);
        float4 a = c4[0], bq = c4[1], c = c4[2], d = c4[3];
        r[0]=a.x;  r[1]=a.y;  r[2]=a.z;  r[3]=a.w;
        r[4]=bq.x; r[5]=bq.y; r[6]=bq.z; r[7]=bq.w;
        r[8]=c.x;  r[9]=c.y;  r[10]=c.z; r[11]=c.w;
        r[12]=d.x; r[13]=d.y; r[14]=d.z; r[15]=d.w;
    }
    // fold lists 512..607 into threads 0..95
    if (t < CAND_LISTS - DIST_NT) {
        float b2[TOPK];
        const float4* c4 = (const float4*)(g_cand + (DIST_NT + t) * TOPK);
        float4 a = c4[0], bq = c4[1], c = c4[2], d = c4[3];
        b2[0]=a.x;  b2[1]=a.y;  b2[2]=a.z;  b2[3]=a.w;
        b2[4]=bq.x; b2[5]=bq.y; b2[6]=bq.z; b2[7]=bq.w;
        b2[8]=c.x;  b2[9]=c.y;  b2[10]=c.z; b2[11]=c.w;
        b2[12]=d.x; b2[13]=d.y; b2[14]=d.z; b2[15]=d.w;
        reg_merge16(r, b2);
    }

    // in-warp 32 -> 1, then 16 warp lists -> 1
    shfl_merge16(r, 16);
    shfl_merge16(r, 8);
    shfl_merge16(r, 4);
    shfl_merge16(r, 2);
    shfl_merge16(r, 1);
    if (lane == 0) {
#pragma unroll
        for (int i = 0; i < TOPK; ++i) swarp[warp * TOPK + i] = r[i];
    }
    __syncthreads();
    if (warp == 0) {
#pragma unroll
        for (int i = 0; i < TOPK; ++i)
            r[i] = (lane < 16) ? swarp[lane * TOPK + i] : FLT_MAX;
        shfl_merge16(r, 16);
        shfl_merge16(r, 8);
        shfl_merge16(r, 4);
        shfl_merge16(r, 2);
        shfl_merge16(r, 1);
        if (lane == 0) {
            float num = 0.0f, den = 0.0f;
#pragma unroll
            for (int i = 0; i < TOPK; ++i) {
                float w = exp_w[i];
                num = fmaf(r[i], w, num);
                den += w;
            }
            out[0] = num / den;
            g_ctr_dist = 0u;
        }
    }
    // reset accumulator for the next graph replay (all blocks have long
    // since read g_enc_raw at their kernel start)
    g_enc_raw[t] = 0.0f;
}

// ---------------------------------------------------------------------------
// Launch.
// Inputs: data[256], mean[256], std[256], memory[131072*512],
//         W[256*512], b[512], exp_w[16]  ->  out[1] float
// ---------------------------------------------------------------------------
extern "C" void kernel_launch(void* const* d_in, const int* in_sizes, int n_in,
                              void* d_out, int out_size) {
    const float* data   = (const float*)d_in[0];
    const float* mean   = (const float*)d_in[1];
    const float* stdv   = (const float*)d_in[2];
    const float* memory = (const float*)d_in[3];
    const float* W      = (const float*)d_in[4];
    const float* b      = (const float*)d_in[5];
    const float* exp_w  = (const float*)d_in[6];
    float* out = (float*)d_out;

    enc_kernel<<<ENC_PARTS, OUT_DIM>>>(data, mean, stdv, W);

    // dist as PDL secondary: may begin (prefetch phase) while enc finishes
    cudaLaunchConfig_t cfg = {};
    cfg.gridDim  = dim3(DIST_BLOCKS, 1, 1);
    cfg.blockDim = dim3(DIST_NT, 1, 1);
    cfg.dynamicSmemBytes = 0;
    cfg.stream = 0;
    cudaLaunchAttribute attrs[1];
    attrs[0].id = cudaLaunchAttributeProgrammaticStreamSerialization;
    attrs[0].val.programmaticStreamSerializationAllowed = 1;
    cfg.attrs = attrs;
    cfg.numAttrs = 1;
    cudaLaunchKernelEx(&cfg, dist_topk_kernel, memory, b, exp_w, out);
}

// round 17
// speedup vs baseline: 1.1686x; 1.0543x over previous
#include <cuda_runtime.h>
#include <float.h>

#define IN_DIM 256
#define OUT_DIM 512
#define MEM_LEN 131072
#define TOPK 16

#define ENC_PARTS 64
#define ROWS_PER_PART (IN_DIM / ENC_PARTS)   // 4

#define DIST_BLOCKS 608                       // 152 SMs * 4 blocks, one wave
#define DIST_NT 512                           // 16 warps
#define WARPS_PER_BLOCK (DIST_NT / 32)
#define NWARPS (DIST_BLOCKS * WARPS_PER_BLOCK) // 9728 warps
#define ROWS_BASE (MEM_LEN / NWARPS)          // 13
#define ROWS_REM  (MEM_LEN % NWARPS)          // 4608 warps do 14

#define CAND_LISTS DIST_BLOCKS                // 608 sorted 16-lists
#define CAND_N (CAND_LISTS * TOPK)

__device__ float g_enc_raw[OUT_DIM];          // zero-init; reset each replay
__device__ float g_cand[CAND_N];
__device__ unsigned int g_ctr_dist;

// ---------------------------------------------------------------------------
// streaming (evict-first) float4 load: ld.global.cs.v4
// ---------------------------------------------------------------------------
__device__ __forceinline__ float4 ldcs4(const float4* p) {
    float4 v;
    asm volatile("ld.global.cs.v4.f32 {%0,%1,%2,%3}, [%4];"
                 : "=f"(v.x), "=f"(v.y), "=f"(v.z), "=f"(v.w) : "l"(p));
    return v;
}

// ---------------------------------------------------------------------------
// bitonic clean of a register-resident 16-array (bitonic -> sorted ascending)
// ---------------------------------------------------------------------------
__device__ __forceinline__ void bitonic_clean16(float* r) {
#pragma unroll
    for (int j = 8; j > 0; j >>= 1) {
#pragma unroll
        for (int i = 0; i < TOPK; ++i) {
            if ((i & j) == 0 && (i ^ j) > i) {
                float lo = fminf(r[i], r[i ^ j]);
                float hi = fmaxf(r[i], r[i ^ j]);
                r[i] = lo; r[i ^ j] = hi;
            }
        }
    }
}

// merge own sorted-16 with register list b (sorted): keep 16 smallest, sorted
__device__ __forceinline__ void reg_merge16(float* r, const float* b) {
#pragma unroll
    for (int i = 0; i < TOPK; ++i) r[i] = fminf(r[i], b[TOPK - 1 - i]);
    bitonic_clean16(r);
}

// merge own sorted-16 with XOR-partner lane's sorted-16; all lanes end with
// the sorted 16 smallest of the union. Branchless.
__device__ __forceinline__ void shfl_merge16(float* r, int off) {
#pragma unroll
    for (int i = 0; i < 8; ++i) {
        float ohi = __shfl_xor_sync(0xFFFFFFFFu, r[15 - i], off);
        float olo = __shfl_xor_sync(0xFFFFFFFFu, r[i], off);
        r[i]      = fminf(r[i], ohi);
        r[15 - i] = fminf(r[15 - i], olo);
    }
    bitonic_clean16(r);
}

__device__ __forceinline__ void prefetch_l2(const void* p) {
    asm volatile("prefetch.global.L2 [%0];" :: "l"(p));
}

// ---------------------------------------------------------------------------
// Kernel 1: GEMV partials via float atomicAdd. Triggers PDL completion at
// entry so the dist kernel's grid can launch and prefetch concurrently.
// ---------------------------------------------------------------------------
__global__ void __launch_bounds__(OUT_DIM, 4)
enc_kernel(const float* __restrict__ data,
           const float* __restrict__ mean,
           const float* __restrict__ stdv,
           const float* __restrict__ W) {
    cudaTriggerProgrammaticLaunchCompletion();

    __shared__ float xn[ROWS_PER_PART];
    int t = threadIdx.x;
    int r0 = blockIdx.x * ROWS_PER_PART;
    if (t < ROWS_PER_PART) {
        int r = r0 + t;
        float s = stdv[r];
        xn[t] = (s == 0.0f) ? 0.0f : (data[r] - mean[r]) / s;
    }
    __syncthreads();
    float acc = 0.0f;
#pragma unroll
    for (int i = 0; i < ROWS_PER_PART; ++i)
        acc = fmaf(xn[i], W[(size_t)(r0 + i) * OUT_DIM + t], acc);
    atomicAdd(&g_enc_raw[t], acc);
}

// ---------------------------------------------------------------------------
// Kernel 2 (PDL secondary): prefetch first row, wait for enc, then the
// R7 dist loop with streaming (evict-first) loads, warp top-16, block merge,
// last-block global merge & loss. 608 x 512, 4/SM, one wave.
// ---------------------------------------------------------------------------
__global__ void __launch_bounds__(DIST_NT, 4)
dist_topk_kernel(const float* __restrict__ memory,
                 const float* __restrict__ b,
                 const float* __restrict__ exp_w,
                 float* __restrict__ out) {
    __shared__ float se[OUT_DIM];
    __shared__ float swarp[WARPS_PER_BLOCK * TOPK];
    __shared__ unsigned int s_ticket;

    int t = threadIdx.x;
    int warp = t >> 5;
    int lane = t & 31;
    int gw   = blockIdx.x * WARPS_PER_BLOCK + warp;    // global warp id

    // warm L2 with this warp's first row while enc still runs (pre-sync:
    // nothing competes for LSU slots here)
    {
        const float4* m0 = (const float4*)(memory + (size_t)gw * OUT_DIM);
        prefetch_l2(&m0[0 * 32 + lane]);
        prefetch_l2(&m0[1 * 32 + lane]);
        prefetch_l2(&m0[2 * 32 + lane]);
        prefetch_l2(&m0[3 * 32 + lane]);
    }

    // wait for enc kernel's atomicAdds to be complete & visible
    cudaGridDependencySynchronize();

    se[t] = tanhf(g_enc_raw[t] + b[t]);     // bias + tanh folded here
    __syncthreads();

    int nrows = ROWS_BASE + (gw < ROWS_REM ? 1 : 0);   // 13 or 14

    const float4* es = (const float4*)se;
    float my = FLT_MAX;   // lane k holds dist of this warp's k-th row

    for (int k = 0; k < nrows; ++k) {
        size_t row = (size_t)gw + (size_t)k * NWARPS;
        const float4* m = (const float4*)(memory + row * OUT_DIM);
        float4 v0 = ldcs4(&m[0 * 32 + lane]);
        float4 v1 = ldcs4(&m[1 * 32 + lane]);
        float4 v2 = ldcs4(&m[2 * 32 + lane]);
        float4 v3 = ldcs4(&m[3 * 32 + lane]);

        float4 e0 = es[0 * 32 + lane];
        float4 e1 = es[1 * 32 + lane];
        float4 e2 = es[2 * 32 + lane];
        float4 e3 = es[3 * 32 + lane];

        float s = 0.0f;
        s += fabsf(v0.x - e0.x) + fabsf(v0.y - e0.y) + fabsf(v0.z - e0.z) + fabsf(v0.w - e0.w);
        s += fabsf(v1.x - e1.x) + fabsf(v1.y - e1.y) + fabsf(v1.z - e1.z) + fabsf(v1.w - e1.w);
        s += fabsf(v2.x - e2.x) + fabsf(v2.y - e2.y) + fabsf(v2.z - e2.z) + fabsf(v2.w - e2.w);
        s += fabsf(v3.x - e3.x) + fabsf(v3.y - e3.y) + fabsf(v3.z - e3.z) + fabsf(v3.w - e3.w);

#pragma unroll
        for (int o = 16; o > 0; o >>= 1)
            s += __shfl_xor_sync(0xFFFFFFFFu, s, o);

        my = (lane == k) ? s : my;
    }

    // warp bitonic sort over 32 lane values (valid + FLT_MAX pad), ascending
#pragma unroll
    for (int k = 2; k <= 32; k <<= 1) {
#pragma unroll
        for (int j = k >> 1; j > 0; j >>= 1) {
            float other = __shfl_xor_sync(0xFFFFFFFFu, my, j);
            bool up = ((lane & k) == 0);
            bool lower = ((lane & j) == 0);
            my = (lower == up) ? fminf(my, other) : fmaxf(my, other);
        }
    }
    if (lane < TOPK) swarp[warp * TOPK + lane] = my;
    __syncthreads();

    // warp 0 merges the 16 per-warp lists -> block's sorted top-16
    if (warp == 0) {
        float r[TOPK];
#pragma unroll
        for (int i = 0; i < TOPK; ++i)
            r[i] = (lane < 16) ? swarp[lane * TOPK + i] : FLT_MAX;
        shfl_merge16(r, 16);
        shfl_merge16(r, 8);
        shfl_merge16(r, 4);
        shfl_merge16(r, 2);
        shfl_merge16(r, 1);
        if (lane == 0) {
            float4* o4 = (float4*)(g_cand + blockIdx.x * TOPK);
            o4[0] = make_float4(r[0], r[1], r[2], r[3]);
            o4[1] = make_float4(r[4], r[5], r[6], r[7]);
            o4[2] = make_float4(r[8], r[9], r[10], r[11]);
            o4[3] = make_float4(r[12], r[13], r[14], r[15]);
        }
    }

    // ---- last-block-done: merge 608 sorted 16-lists + loss ----
    __threadfence();
    __syncthreads();
    if (t == 0) s_ticket = atomicAdd(&g_ctr_dist, 1u);
    __syncthreads();
    if (s_ticket != DIST_BLOCKS - 1) return;
    __threadfence();

    float r[TOPK];
    {
        const float4* c4 = (const float4*)(g_cand + t * TOPK);
        float4 a = c4[0], bq = c4[1], c = c4[2], d = c4[3];
        r[0]=a.x;  r[1]=a.y;  r[2]=a.z;  r[3]=a.w;
        r[4]=bq.x; r[5]=bq.y; r[6]=bq.z; r[7]=bq.w;
        r[8]=c.x;  r[9]=c.y;  r[10]=c.z; r[11]=c.w;
        r[12]=d.x; r[13]=d.y; r[14]=d.z; r[15]=d.w;
    }
    // fold lists 512..607 into threads 0..95
    if (t < CAND_LISTS - DIST_NT) {
        float b2[TOPK];
        const float4* c4 = (const float4*)(g_cand + (DIST_NT + t) * TOPK);
        float4 a = c4[0], bq = c4[1], c = c4[2], d = c4[3];
        b2[0]=a.x;  b2[1]=a.y;  b2[2]=a.z;  b2[3]=a.w;
        b2[4]=bq.x; b2[5]=bq.y; b2[6]=bq.z; b2[7]=bq.w;
        b2[8]=c.x;  b2[9]=c.y;  b2[10]=c.z; b2[11]=c.w;
        b2[12]=d.x; b2[13]=d.y; b2[14]=d.z; b2[15]=d.w;
        reg_merge16(r, b2);
    }

    // in-warp 32 -> 1, then 16 warp lists -> 1
    shfl_merge16(r, 16);
    shfl_merge16(r, 8);
    shfl_merge16(r, 4);
    shfl_merge16(r, 2);
    shfl_merge16(r, 1);
    if (lane == 0) {
#pragma unroll
        for (int i = 0; i < TOPK; ++i) swarp[warp * TOPK + i] = r[i];
    }
    __syncthreads();
    if (warp == 0) {
#pragma unroll
        for (int i = 0; i < TOPK; ++i)
            r[i] = (lane < 16) ? swarp[lane * TOPK + i] : FLT_MAX;
        shfl_merge16(r, 16);
        shfl_merge16(r, 8);
        shfl_merge16(r, 4);
        shfl_merge16(r, 2);
        shfl_merge16(r, 1);
        if (lane == 0) {
            float num = 0.0f, den = 0.0f;
#pragma unroll
            for (int i = 0; i < TOPK; ++i) {
                float w = exp_w[i];
                num = fmaf(r[i], w, num);
                den += w;
            }
            out[0] = num / den;
            g_ctr_dist = 0u;
        }
    }
    // reset accumulator for the next graph replay
    g_enc_raw[t] = 0.0f;
}

// ---------------------------------------------------------------------------
// Launch.
// Inputs: data[256], mean[256], std[256], memory[131072*512],
//         W[256*512], b[512], exp_w[16]  ->  out[1] float
// ---------------------------------------------------------------------------
extern "C" void kernel_launch(void* const* d_in, const int* in_sizes, int n_in,
                              void* d_out, int out_size) {
    const float* data   = (const float*)d_in[0];
    const float* mean   = (const float*)d_in[1];
    const float* stdv   = (const float*)d_in[2];
    const float* memory = (const float*)d_in[3];
    const float* W      = (const float*)d_in[4];
    const float* b      = (const float*)d_in[5];
    const float* exp_w  = (const float*)d_in[6];
    float* out = (float*)d_out;

    enc_kernel<<<ENC_PARTS, OUT_DIM>>>(data, mean, stdv, W);

    // dist as PDL secondary: may begin (prefetch phase) while enc finishes
    cudaLaunchConfig_t cfg = {};
    cfg.gridDim  = dim3(DIST_BLOCKS, 1, 1);
    cfg.blockDim = dim3(DIST_NT, 1, 1);
    cfg.dynamicSmemBytes = 0;
    cfg.stream = 0;
    cudaLaunchAttribute attrs[1];
    attrs[0].id = cudaLaunchAttributeProgrammaticStreamSerialization;
    attrs[0].val.programmaticStreamSerializationAllowed = 1;
    cfg.attrs = attrs;
    cfg.numAttrs = 1;
    cudaLaunchKernelEx(&cfg, dist_topk_kernel, memory, b, exp_w, out);
}